// round 13
// baseline (speedup 1.0000x reference)
#include <cuda_runtime.h>
#include <cuda_fp16.h>
#include <cuda_bf16.h>
#include <cstdint>

#define N_NODES 100000
#define N_EDGES 1250000
#define D 64
#define PAD 64

typedef unsigned long long u64;

// ---- scratch (no allocations allowed) ----
__device__ int    g_deg_out[N_NODES];
__device__ int    g_cnt[N_NODES];             // in-degree, built during scatter
__device__ int    g_esrc[N_NODES * PAD];      // padded per-dst buckets
__device__ __half g_h[N_NODES * D];           // projected rows (fp16, UNscaled)

// ------- fused: out-degree histogram + in-degree count + padded scatter -------
__global__ void k_build(const int* __restrict__ src, const int* __restrict__ dst) {
    int i = blockIdx.x * blockDim.x + threadIdx.x;
    if (i < N_EDGES / 4) {
        int4 s = ((const int4*)src)[i];
        int4 d = ((const int4*)dst)[i];
        atomicAdd(&g_deg_out[s.x], 1); atomicAdd(&g_deg_out[s.y], 1);
        atomicAdd(&g_deg_out[s.z], 1); atomicAdd(&g_deg_out[s.w], 1);
        int p;
        p = atomicAdd(&g_cnt[d.x], 1); if (p < PAD) g_esrc[d.x * PAD + p] = s.x;
        p = atomicAdd(&g_cnt[d.y], 1); if (p < PAD) g_esrc[d.y * PAD + p] = s.y;
        p = atomicAdd(&g_cnt[d.z], 1); if (p < PAD) g_esrc[d.z * PAD + p] = s.z;
        p = atomicAdd(&g_cnt[d.w], 1); if (p < PAD) g_esrc[d.w * PAD + p] = s.w;
    }
}

// ====== projection via mma.sync (HMMA), 3xBF16 split ======
// A staged in smem (uint2 hi/lo per col-pair); B pre-packed per-fragment (uint4/lane).
#define PROJ_M 128
#define PROJ_BLOCKS ((N_NODES + PROJ_M - 1) / PROJ_M)   // 782
#define APITCH 36
#define SA_BYTES (128 * APITCH * 8)                     // 36864
#define SB_OFF   SA_BYTES
#define PROJ_SMEM (SA_BYTES + 32 * 32 * 16)             // 53248

__device__ __forceinline__ void mma_bf16(float* d, const uint32_t* a, uint32_t b0, uint32_t b1) {
    asm volatile(
        "mma.sync.aligned.m16n8k16.row.col.f32.bf16.bf16.f32 "
        "{%0,%1,%2,%3}, {%4,%5,%6,%7}, {%8,%9}, {%0,%1,%2,%3};"
        : "+f"(d[0]), "+f"(d[1]), "+f"(d[2]), "+f"(d[3])
        : "r"(a[0]), "r"(a[1]), "r"(a[2]), "r"(a[3]), "r"(b0), "r"(b1));
}
__device__ __forceinline__ uint32_t b2u(__nv_bfloat162 h) { return *(uint32_t*)&h; }

__global__ void __launch_bounds__(256, 4)
k_proj(const float* __restrict__ feat, const float* __restrict__ weight) {
    extern __shared__ char smem[];
    uint2* sA = (uint2*)smem;                  // [128][APITCH] (hi,lo) col-pairs
    uint4* sB = (uint4*)(smem + SB_OFF);       // [32 frags][32 lanes] (b0h,b1h,b0l,b1l)

    int tid  = threadIdx.x;
    int wid  = tid >> 5, lane = tid & 31;
    int B0   = blockIdx.x * PROJ_M;

    // ---- stage B fragments in MMA register order ----
    #pragma unroll
    for (int i = tid; i < 1024; i += 256) {
        int f  = i >> 5, l = i & 31;
        int ks = f >> 3, nt = f & 7;
        int n  = nt * 8 + (l >> 2);
        int k0 = ks * 16 + (l & 3) * 2;
        float w00 = weight[k0 * 64 + n],       w01 = weight[(k0 + 1) * 64 + n];
        float w10 = weight[(k0 + 8) * 64 + n], w11 = weight[(k0 + 9) * 64 + n];
        __nv_bfloat162 h0 = __floats2bfloat162_rn(w00, w01);
        float2 f0 = __bfloat1622float2(h0);
        __nv_bfloat162 l0 = __floats2bfloat162_rn(w00 - f0.x, w01 - f0.y);
        __nv_bfloat162 h1 = __floats2bfloat162_rn(w10, w11);
        float2 f1 = __bfloat1622float2(h1);
        __nv_bfloat162 l1 = __floats2bfloat162_rn(w10 - f1.x, w11 - f1.y);
        sB[i] = make_uint4(b2u(h0), b2u(h1), b2u(l0), b2u(l1));
    }

    // ---- stage A: coalesced float4 loads, split hi/lo, pack (hi,lo) uint2 ----
    #pragma unroll
    for (int it = 0; it < 8; it++) {
        int idx = tid + it * 256;
        int row = idx >> 4;
        int c4  = idx & 15;
        int gr  = B0 + row;
        float4 v = make_float4(0.f, 0.f, 0.f, 0.f);
        if (gr < N_NODES) v = ((const float4*)feat)[gr * 16 + c4];
        __nv_bfloat162 h01 = __floats2bfloat162_rn(v.x, v.y);
        __nv_bfloat162 h23 = __floats2bfloat162_rn(v.z, v.w);
        float2 f01 = __bfloat1622float2(h01);
        float2 f23 = __bfloat1622float2(h23);
        __nv_bfloat162 l01 = __floats2bfloat162_rn(v.x - f01.x, v.y - f01.y);
        __nv_bfloat162 l23 = __floats2bfloat162_rn(v.z - f23.x, v.w - f23.y);
        sA[row * APITCH + c4 * 2 + 0] = make_uint2(b2u(h01), b2u(l01));
        sA[row * APITCH + c4 * 2 + 1] = make_uint2(b2u(h23), b2u(l23));
    }
    __syncthreads();

    int g   = lane >> 2;
    int tig = lane & 3;
    int lr0 = wid * 16 + g;
    int lr1 = lr0 + 8;
    int r0  = B0 + lr0;
    int r1  = B0 + lr1;
    bool v0 = r0 < N_NODES, v1 = r1 < N_NODES;

    float acc[8][4];
    #pragma unroll
    for (int n = 0; n < 8; n++)
        #pragma unroll
        for (int q = 0; q < 4; q++) acc[n][q] = 0.f;

    #pragma unroll
    for (int ks = 0; ks < 4; ks++) {
        uint2 p0 = sA[lr0 * APITCH + ks * 8 + tig];
        uint2 p1 = sA[lr1 * APITCH + ks * 8 + tig];
        uint2 p2 = sA[lr0 * APITCH + ks * 8 + tig + 4];
        uint2 p3 = sA[lr1 * APITCH + ks * 8 + tig + 4];
        uint32_t aHi[4] = {p0.x, p1.x, p2.x, p3.x};
        uint32_t aLo[4] = {p0.y, p1.y, p2.y, p3.y};

        #pragma unroll
        for (int nt = 0; nt < 8; nt++) {
            uint4 q = sB[(ks * 8 + nt) * 32 + lane];   // one LDS.128, conflict-free
            mma_bf16(acc[nt], aHi, q.x, q.y);
            mma_bf16(acc[nt], aHi, q.z, q.w);
            mma_bf16(acc[nt], aLo, q.x, q.y);
        }
    }

    #pragma unroll
    for (int nt = 0; nt < 8; nt++) {
        int col = nt * 8 + tig * 2;
        if (v0) {
            __half2 p = __floats2half2_rn(acc[nt][0], acc[nt][1]);
            *(uint32_t*)&g_h[r0 * 64 + col] = *(uint32_t*)&p;
        }
        if (v1) {
            __half2 p = __floats2half2_rn(acc[nt][2], acc[nt][3]);
            *(uint32_t*)&g_h[r1 * 64 + col] = *(uint32_t*)&p;
        }
    }
}

// ------- gather: 8 lanes/node, 4 nodes/warp; per-edge src-degree scaling -------
__device__ __forceinline__ void fma8(float* a, uint4 v, float sc) {
    float2 f;
    f = __half22float2(*(__half2*)&v.x); a[0] = fmaf(f.x, sc, a[0]); a[1] = fmaf(f.y, sc, a[1]);
    f = __half22float2(*(__half2*)&v.y); a[2] = fmaf(f.x, sc, a[2]); a[3] = fmaf(f.y, sc, a[3]);
    f = __half22float2(*(__half2*)&v.z); a[4] = fmaf(f.x, sc, a[4]); a[5] = fmaf(f.y, sc, a[5]);
    f = __half22float2(*(__half2*)&v.w); a[6] = fmaf(f.x, sc, a[6]); a[7] = fmaf(f.y, sc, a[7]);
}

__global__ void __launch_bounds__(256)
k_gather(const float* __restrict__ bias, float* __restrict__ out) {
    int warp = (blockIdx.x * blockDim.x + threadIdx.x) >> 5;
    int lane = threadIdx.x & 31;
    int grp  = lane >> 3;
    int sub  = lane & 7;
    int node = warp * 4 + grp;
    if (node >= N_NODES) return;

    int deg = min(g_cnt[node], PAD);
    int beg = node * PAD;
    const uint4* __restrict__ H4 = (const uint4*)g_h;

    float a0[8] = {0.f, 0.f, 0.f, 0.f, 0.f, 0.f, 0.f, 0.f};
    float a1[8] = {0.f, 0.f, 0.f, 0.f, 0.f, 0.f, 0.f, 0.f};

    int e = 0;
    for (; e + 4 <= deg; e += 4) {
        int4 s = *(const int4*)&g_esrc[beg + e];
        int d0 = __ldg(&g_deg_out[s.x]);
        int d1 = __ldg(&g_deg_out[s.y]);
        int d2 = __ldg(&g_deg_out[s.z]);
        int d3 = __ldg(&g_deg_out[s.w]);
        uint4 v0 = __ldg(&H4[s.x * 8 + sub]);
        uint4 v1 = __ldg(&H4[s.y * 8 + sub]);
        uint4 v2 = __ldg(&H4[s.z * 8 + sub]);
        uint4 v3 = __ldg(&H4[s.w * 8 + sub]);
        float c0 = rsqrtf((float)max(d0, 1));
        float c1 = rsqrtf((float)max(d1, 1));
        float c2 = rsqrtf((float)max(d2, 1));
        float c3 = rsqrtf((float)max(d3, 1));
        fma8(a0, v0, c0);
        fma8(a1, v1, c1);
        fma8(a0, v2, c2);
        fma8(a1, v3, c3);
    }
    for (; e < deg; e++) {
        int s = __ldg(&g_esrc[beg + e]);
        int d = __ldg(&g_deg_out[s]);
        uint4 v = __ldg(&H4[s * 8 + sub]);
        fma8(a0, v, rsqrtf((float)max(d, 1)));
    }

    float sc = rsqrtf((float)max(deg, 1));
    float4 b0 = *(const float4*)&bias[sub * 8];
    float4 b1 = *(const float4*)&bias[sub * 8 + 4];
    float4 o0, o1;
    o0.x = (a0[0] + a1[0]) * sc + b0.x;
    o0.y = (a0[1] + a1[1]) * sc + b0.y;
    o0.z = (a0[2] + a1[2]) * sc + b0.z;
    o0.w = (a0[3] + a1[3]) * sc + b0.w;
    o1.x = (a0[4] + a1[4]) * sc + b1.x;
    o1.y = (a0[5] + a1[5]) * sc + b1.y;
    o1.z = (a0[6] + a1[6]) * sc + b1.z;
    o1.w = (a0[7] + a1[7]) * sc + b1.w;
    *(float4*)&out[node * 64 + sub * 8]     = o0;
    *(float4*)&out[node * 64 + sub * 8 + 4] = o1;
}

// ---------------- stream/event resources ----------------
struct GcnRes {
    cudaStream_t s2 = nullptr;
    cudaEvent_t  ev_fork = nullptr, ev_join = nullptr;
    GcnRes() {
        cudaStreamCreateWithFlags(&s2, cudaStreamNonBlocking);
        cudaEventCreateWithFlags(&ev_fork, cudaEventDisableTiming);
        cudaEventCreateWithFlags(&ev_join, cudaEventDisableTiming);
    }
};
static GcnRes g_res;

extern "C" void kernel_launch(void* const* d_in, const int* in_sizes, int n_in,
                              void* d_out, int out_size) {
    const float* features = (const float*)d_in[0];
    const float* weight   = (const float*)d_in[1];
    const float* bias     = (const float*)d_in[2];
    const int*   src      = (const int*)d_in[3];
    const int*   dst      = (const int*)d_in[4];
    float* out = (float*)d_out;

    if (!g_res.s2) {
        cudaStreamCreateWithFlags(&g_res.s2, cudaStreamNonBlocking);
        cudaEventCreateWithFlags(&g_res.ev_fork, cudaEventDisableTiming);
        cudaEventCreateWithFlags(&g_res.ev_join, cudaEventDisableTiming);
    }

    static void* p_deg_out = nullptr;
    static void* p_cnt     = nullptr;
    static bool  attr_set  = false;
    if (!p_deg_out) {
        cudaGetSymbolAddress(&p_deg_out, g_deg_out);
        cudaGetSymbolAddress(&p_cnt,     g_cnt);
    }
    if (!attr_set) {
        cudaFuncSetAttribute(k_proj, cudaFuncAttributeMaxDynamicSharedMemorySize, PROJ_SMEM);
        attr_set = true;
    }

    cudaStream_t ms = 0;
    cudaStream_t s2 = g_res.s2;

    // fork: proj has NO dependencies — runs concurrently on s2
    cudaEventRecord(g_res.ev_fork, ms);
    cudaStreamWaitEvent(s2, g_res.ev_fork, 0);
    k_proj <<<PROJ_BLOCKS, 256, PROJ_SMEM, s2>>>(features, weight);
    cudaEventRecord(g_res.ev_join, s2);

    // main stream: CSR build (all atomics in one pass)
    cudaMemsetAsync(p_deg_out, 0, N_NODES * sizeof(int), ms);
    cudaMemsetAsync(p_cnt,     0, N_NODES * sizeof(int), ms);
    k_build <<<(N_EDGES / 4 + 255) / 256, 256, 0, ms>>>(src, dst);

    // join + gather
    cudaStreamWaitEvent(ms, g_res.ev_join, 0);
    k_gather <<<(N_NODES + 31) / 32, 256, 0, ms>>>(bias, out);
}

// round 14
// speedup vs baseline: 1.2218x; 1.2218x over previous
#include <cuda_runtime.h>
#include <cuda_fp16.h>
#include <cuda_bf16.h>
#include <cstdint>

#define N_NODES 100000
#define N_EDGES 1250000
#define D 64
#define PAD 64

typedef unsigned long long u64;

// ---- scratch (no allocations allowed; zero-initialized at load) ----
__device__ int    g_deg_out[N_NODES];
__device__ int    g_cnt[N_NODES];             // in-degree, built during scatter
__device__ int    g_esrc[N_NODES * PAD];      // padded per-dst buckets
__device__ __half g_h[N_NODES * D];           // projected rows (fp16, UNscaled)

// ------- fused: out-degree histogram + in-degree count + padded scatter -------
__global__ void k_build(const int* __restrict__ src, const int* __restrict__ dst) {
    int i = blockIdx.x * blockDim.x + threadIdx.x;
    if (i < N_EDGES / 4) {
        int4 s = ((const int4*)src)[i];
        int4 d = ((const int4*)dst)[i];
        atomicAdd(&g_deg_out[s.x], 1); atomicAdd(&g_deg_out[s.y], 1);
        atomicAdd(&g_deg_out[s.z], 1); atomicAdd(&g_deg_out[s.w], 1);
        int p;
        p = atomicAdd(&g_cnt[d.x], 1); if (p < PAD) g_esrc[d.x * PAD + p] = s.x;
        p = atomicAdd(&g_cnt[d.y], 1); if (p < PAD) g_esrc[d.y * PAD + p] = s.y;
        p = atomicAdd(&g_cnt[d.z], 1); if (p < PAD) g_esrc[d.z * PAD + p] = s.z;
        p = atomicAdd(&g_cnt[d.w], 1); if (p < PAD) g_esrc[d.w * PAD + p] = s.w;
    }
}

// ------- trailing zero: reset counters for the next graph replay -------
__global__ void k_zero() {
    int i = blockIdx.x * blockDim.x + threadIdx.x;
    if (i < N_NODES / 4) {
        ((int4*)g_deg_out)[i] = make_int4(0, 0, 0, 0);
        ((int4*)g_cnt)[i]     = make_int4(0, 0, 0, 0);
    }
}

// ====== projection via mma.sync (HMMA), 3xBF16 split ======
#define PROJ_M 128
#define PROJ_BLOCKS ((N_NODES + PROJ_M - 1) / PROJ_M)   // 782
#define APITCH 36
#define SA_BYTES (128 * APITCH * 8)                     // 36864
#define SB_OFF   SA_BYTES
#define PROJ_SMEM (SA_BYTES + 32 * 32 * 16)             // 53248

__device__ __forceinline__ void mma_bf16(float* d, const uint32_t* a, uint32_t b0, uint32_t b1) {
    asm volatile(
        "mma.sync.aligned.m16n8k16.row.col.f32.bf16.bf16.f32 "
        "{%0,%1,%2,%3}, {%4,%5,%6,%7}, {%8,%9}, {%0,%1,%2,%3};"
        : "+f"(d[0]), "+f"(d[1]), "+f"(d[2]), "+f"(d[3])
        : "r"(a[0]), "r"(a[1]), "r"(a[2]), "r"(a[3]), "r"(b0), "r"(b1));
}
__device__ __forceinline__ uint32_t b2u(__nv_bfloat162 h) { return *(uint32_t*)&h; }

__global__ void __launch_bounds__(256, 4)
k_proj(const float* __restrict__ feat, const float* __restrict__ weight) {
    extern __shared__ char smem[];
    uint2* sA = (uint2*)smem;                  // [128][APITCH] (hi,lo) col-pairs
    uint4* sB = (uint4*)(smem + SB_OFF);       // [32 frags][32 lanes]

    int tid  = threadIdx.x;
    int wid  = tid >> 5, lane = tid & 31;
    int B0   = blockIdx.x * PROJ_M;

    // ---- stage B fragments in MMA register order ----
    #pragma unroll
    for (int i = tid; i < 1024; i += 256) {
        int f  = i >> 5, l = i & 31;
        int ks = f >> 3, nt = f & 7;
        int n  = nt * 8 + (l >> 2);
        int k0 = ks * 16 + (l & 3) * 2;
        float w00 = weight[k0 * 64 + n],       w01 = weight[(k0 + 1) * 64 + n];
        float w10 = weight[(k0 + 8) * 64 + n], w11 = weight[(k0 + 9) * 64 + n];
        __nv_bfloat162 h0 = __floats2bfloat162_rn(w00, w01);
        float2 f0 = __bfloat1622float2(h0);
        __nv_bfloat162 l0 = __floats2bfloat162_rn(w00 - f0.x, w01 - f0.y);
        __nv_bfloat162 h1 = __floats2bfloat162_rn(w10, w11);
        float2 f1 = __bfloat1622float2(h1);
        __nv_bfloat162 l1 = __floats2bfloat162_rn(w10 - f1.x, w11 - f1.y);
        sB[i] = make_uint4(b2u(h0), b2u(h1), b2u(l0), b2u(l1));
    }

    // ---- stage A: coalesced float4 loads, split hi/lo, pack (hi,lo) uint2 ----
    #pragma unroll
    for (int it = 0; it < 8; it++) {
        int idx = tid + it * 256;
        int row = idx >> 4;
        int c4  = idx & 15;
        int gr  = B0 + row;
        float4 v = make_float4(0.f, 0.f, 0.f, 0.f);
        if (gr < N_NODES) v = ((const float4*)feat)[gr * 16 + c4];
        __nv_bfloat162 h01 = __floats2bfloat162_rn(v.x, v.y);
        __nv_bfloat162 h23 = __floats2bfloat162_rn(v.z, v.w);
        float2 f01 = __bfloat1622float2(h01);
        float2 f23 = __bfloat1622float2(h23);
        __nv_bfloat162 l01 = __floats2bfloat162_rn(v.x - f01.x, v.y - f01.y);
        __nv_bfloat162 l23 = __floats2bfloat162_rn(v.z - f23.x, v.w - f23.y);
        sA[row * APITCH + c4 * 2 + 0] = make_uint2(b2u(h01), b2u(l01));
        sA[row * APITCH + c4 * 2 + 1] = make_uint2(b2u(h23), b2u(l23));
    }
    __syncthreads();

    int g   = lane >> 2;
    int tig = lane & 3;
    int lr0 = wid * 16 + g;
    int lr1 = lr0 + 8;
    int r0  = B0 + lr0;
    int r1  = B0 + lr1;
    bool v0 = r0 < N_NODES, v1 = r1 < N_NODES;

    float acc[8][4];
    #pragma unroll
    for (int n = 0; n < 8; n++)
        #pragma unroll
        for (int q = 0; q < 4; q++) acc[n][q] = 0.f;

    #pragma unroll
    for (int ks = 0; ks < 4; ks++) {
        uint2 p0 = sA[lr0 * APITCH + ks * 8 + tig];
        uint2 p1 = sA[lr1 * APITCH + ks * 8 + tig];
        uint2 p2 = sA[lr0 * APITCH + ks * 8 + tig + 4];
        uint2 p3 = sA[lr1 * APITCH + ks * 8 + tig + 4];
        uint32_t aHi[4] = {p0.x, p1.x, p2.x, p3.x};
        uint32_t aLo[4] = {p0.y, p1.y, p2.y, p3.y};

        #pragma unroll
        for (int nt = 0; nt < 8; nt++) {
            uint4 q = sB[(ks * 8 + nt) * 32 + lane];   // one LDS.128, conflict-free
            mma_bf16(acc[nt], aHi, q.x, q.y);
            mma_bf16(acc[nt], aHi, q.z, q.w);
            mma_bf16(acc[nt], aLo, q.x, q.y);
        }
    }

    #pragma unroll
    for (int nt = 0; nt < 8; nt++) {
        int col = nt * 8 + tig * 2;
        if (v0) {
            __half2 p = __floats2half2_rn(acc[nt][0], acc[nt][1]);
            *(uint32_t*)&g_h[r0 * 64 + col] = *(uint32_t*)&p;
        }
        if (v1) {
            __half2 p = __floats2half2_rn(acc[nt][2], acc[nt][3]);
            *(uint32_t*)&g_h[r1 * 64 + col] = *(uint32_t*)&p;
        }
    }
}

// ------- gather: 8 lanes/node, 4 nodes/warp; per-edge src-degree scaling -------
__device__ __forceinline__ void fma8(float* a, uint4 v, float sc) {
    float2 f;
    f = __half22float2(*(__half2*)&v.x); a[0] = fmaf(f.x, sc, a[0]); a[1] = fmaf(f.y, sc, a[1]);
    f = __half22float2(*(__half2*)&v.y); a[2] = fmaf(f.x, sc, a[2]); a[3] = fmaf(f.y, sc, a[3]);
    f = __half22float2(*(__half2*)&v.z); a[4] = fmaf(f.x, sc, a[4]); a[5] = fmaf(f.y, sc, a[5]);
    f = __half22float2(*(__half2*)&v.w); a[6] = fmaf(f.x, sc, a[6]); a[7] = fmaf(f.y, sc, a[7]);
}

__global__ void __launch_bounds__(256)
k_gather(const float* __restrict__ bias, float* __restrict__ out) {
    int warp = (blockIdx.x * blockDim.x + threadIdx.x) >> 5;
    int lane = threadIdx.x & 31;
    int grp  = lane >> 3;
    int sub  = lane & 7;
    int node = warp * 4 + grp;
    if (node >= N_NODES) return;

    int deg = min(g_cnt[node], PAD);
    int beg = node * PAD;
    const uint4* __restrict__ H4 = (const uint4*)g_h;

    float a0[8] = {0.f, 0.f, 0.f, 0.f, 0.f, 0.f, 0.f, 0.f};
    float a1[8] = {0.f, 0.f, 0.f, 0.f, 0.f, 0.f, 0.f, 0.f};

    int e = 0;
    for (; e + 4 <= deg; e += 4) {
        int4 s = *(const int4*)&g_esrc[beg + e];
        int d0 = __ldg(&g_deg_out[s.x]);
        int d1 = __ldg(&g_deg_out[s.y]);
        int d2 = __ldg(&g_deg_out[s.z]);
        int d3 = __ldg(&g_deg_out[s.w]);
        uint4 v0 = __ldg(&H4[s.x * 8 + sub]);
        uint4 v1 = __ldg(&H4[s.y * 8 + sub]);
        uint4 v2 = __ldg(&H4[s.z * 8 + sub]);
        uint4 v3 = __ldg(&H4[s.w * 8 + sub]);
        float c0 = rsqrtf((float)max(d0, 1));
        float c1 = rsqrtf((float)max(d1, 1));
        float c2 = rsqrtf((float)max(d2, 1));
        float c3 = rsqrtf((float)max(d3, 1));
        fma8(a0, v0, c0);
        fma8(a1, v1, c1);
        fma8(a0, v2, c2);
        fma8(a1, v3, c3);
    }
    for (; e < deg; e++) {
        int s = __ldg(&g_esrc[beg + e]);
        int d = __ldg(&g_deg_out[s]);
        uint4 v = __ldg(&H4[s * 8 + sub]);
        fma8(a0, v, rsqrtf((float)max(d, 1)));
    }

    float sc = rsqrtf((float)max(deg, 1));
    float4 b0 = *(const float4*)&bias[sub * 8];
    float4 b1 = *(const float4*)&bias[sub * 8 + 4];
    float4 o0, o1;
    o0.x = (a0[0] + a1[0]) * sc + b0.x;
    o0.y = (a0[1] + a1[1]) * sc + b0.y;
    o0.z = (a0[2] + a1[2]) * sc + b0.z;
    o0.w = (a0[3] + a1[3]) * sc + b0.w;
    o1.x = (a0[4] + a1[4]) * sc + b1.x;
    o1.y = (a0[5] + a1[5]) * sc + b1.y;
    o1.z = (a0[6] + a1[6]) * sc + b1.z;
    o1.w = (a0[7] + a1[7]) * sc + b1.w;
    *(float4*)&out[node * 64 + sub * 8]     = o0;
    *(float4*)&out[node * 64 + sub * 8 + 4] = o1;
}

// ---------------- stream/event resources ----------------
struct GcnRes {
    cudaStream_t s_hi = nullptr;   // build + gather (highest priority)
    cudaStream_t s_lo = nullptr;   // proj (lowest priority)
    cudaEvent_t  ev_fork = nullptr, ev_proj = nullptr, ev_done = nullptr;
    GcnRes() {
        int lo_pri, hi_pri;
        cudaDeviceGetStreamPriorityRange(&lo_pri, &hi_pri);
        cudaStreamCreateWithPriority(&s_hi, cudaStreamNonBlocking, hi_pri);
        cudaStreamCreateWithPriority(&s_lo, cudaStreamNonBlocking, lo_pri);
        cudaEventCreateWithFlags(&ev_fork, cudaEventDisableTiming);
        cudaEventCreateWithFlags(&ev_proj, cudaEventDisableTiming);
        cudaEventCreateWithFlags(&ev_done, cudaEventDisableTiming);
    }
};
static GcnRes g_res;

extern "C" void kernel_launch(void* const* d_in, const int* in_sizes, int n_in,
                              void* d_out, int out_size) {
    const float* features = (const float*)d_in[0];
    const float* weight   = (const float*)d_in[1];
    const float* bias     = (const float*)d_in[2];
    const int*   src      = (const int*)d_in[3];
    const int*   dst      = (const int*)d_in[4];
    float* out = (float*)d_out;

    if (!g_res.s_hi) {
        int lo_pri, hi_pri;
        cudaDeviceGetStreamPriorityRange(&lo_pri, &hi_pri);
        cudaStreamCreateWithPriority(&g_res.s_hi, cudaStreamNonBlocking, hi_pri);
        cudaStreamCreateWithPriority(&g_res.s_lo, cudaStreamNonBlocking, lo_pri);
        cudaEventCreateWithFlags(&g_res.ev_fork, cudaEventDisableTiming);
        cudaEventCreateWithFlags(&g_res.ev_proj, cudaEventDisableTiming);
        cudaEventCreateWithFlags(&g_res.ev_done, cudaEventDisableTiming);
    }
    static bool attr_set = false;
    if (!attr_set) {
        cudaFuncSetAttribute(k_proj, cudaFuncAttributeMaxDynamicSharedMemorySize, PROJ_SMEM);
        attr_set = true;
    }

    cudaStream_t ms = 0;

    // fork from capture stream
    cudaEventRecord(g_res.ev_fork, ms);
    cudaStreamWaitEvent(g_res.s_hi, g_res.ev_fork, 0);
    cudaStreamWaitEvent(g_res.s_lo, g_res.ev_fork, 0);

    // high-priority critical path: build immediately (counters pre-zeroed)
    k_build <<<(N_EDGES / 4 + 255) / 256, 256, 0, g_res.s_hi>>>(src, dst);

    // low-priority: projection fills spare SM slots
    k_proj <<<PROJ_BLOCKS, 256, PROJ_SMEM, g_res.s_lo>>>(features, weight);
    cudaEventRecord(g_res.ev_proj, g_res.s_lo);

    // join proj into critical path, then gather, then reset counters for next replay
    cudaStreamWaitEvent(g_res.s_hi, g_res.ev_proj, 0);
    k_gather <<<(N_NODES + 31) / 32, 256, 0, g_res.s_hi>>>(bias, out);
    k_zero   <<<(N_NODES / 4 + 255) / 256, 256, 0, g_res.s_hi>>>();
    cudaEventRecord(g_res.ev_done, g_res.s_hi);

    // rejoin capture stream
    cudaStreamWaitEvent(ms, g_res.ev_done, 0);
}